// round 9
// baseline (speedup 1.0000x reference)
#include <cuda_runtime.h>
#include <cuda_bf16.h>

#define BB 128   // batch
#define NN 50    // entities per doc
#define KK 20    // neighbors
#define DD 128   // embedding dim
#define NK (NN*KK)          // 1000
#define BN (BB*NN)          // 6400
#define TOT (BB*NN*KK)      // 128000

typedef unsigned long long ull;

// scratch
__device__ float g_exp[TOT];          // transposed: exp(logit)[nk][b]
__device__ float g_den[1024];         // softmax denominators per (n,k)
__device__ float g_ee_dot[BN];
__device__ float g_rel_dot[128];      // R=100, padded
__device__ float g_agg[BN * 2 * DD];  // [bn][256] = [ee | weighted-nb-sum]
__device__ ull   g_Wdup[2 * DD * DD]; // W_conv with each scalar duplicated (w,w)
__device__ float g_part[2][BN * DD];  // K-split partial sums

// ---- packed f32x2 helpers (sm_103a) --------------------------------------
__device__ __forceinline__ ull pack2(float lo, float hi) {
    ull r;
    asm("mov.b64 %0, {%1, %2};" : "=l"(r) : "f"(lo), "f"(hi));
    return r;
}
__device__ __forceinline__ void unpack2(ull v, float& lo, float& hi) {
    asm("mov.b64 {%0, %1}, %2;" : "=f"(lo), "=f"(hi) : "l"(v));
}
__device__ __forceinline__ ull fma2(ull a, ull b, ull c) {
    ull d;
    asm("fma.rn.f32x2 %0, %1, %2, %3;" : "=l"(d) : "l"(a), "l"(b), "l"(c));
    return d;
}

// ---------------------------------------------------------------------------
// K0: zero g_den; ee_dot[bn] = dot(ee, w0); rel_dot[r] = dot(rel_emb[r], w2)
// ---------------------------------------------------------------------------
__global__ __launch_bounds__(256) void k_pre(
    const int* __restrict__ entity_ids,
    const float* __restrict__ ent_emb,
    const float* __restrict__ rel_emb,
    const float* __restrict__ W_att)
{
    int gtid = blockIdx.x * 256 + threadIdx.x;
    if (gtid < 1024) g_den[gtid] = 0.0f;

    int warp = gtid >> 5;
    int lane = threadIdx.x & 31;
    if (warp >= BN + 100) return;

    const float4* row;
    const float4* w;
    if (warp < BN) {
        int eid = entity_ids[warp];
        row = (const float4*)(ent_emb + (size_t)eid * DD);
        w   = (const float4*)(W_att);            // w0
    } else {
        row = (const float4*)(rel_emb + (size_t)(warp - BN) * DD);
        w   = (const float4*)(W_att + 2 * DD);   // w2
    }
    float4 a = row[lane], wv = w[lane];
    float s = a.x*wv.x + a.y*wv.y + a.z*wv.z + a.w*wv.w;
    #pragma unroll
    for (int off = 16; off > 0; off >>= 1)
        s += __shfl_xor_sync(0xffffffffu, s, off);
    if (lane == 0) {
        if (warp < BN) g_ee_dot[warp] = s;
        else           g_rel_dot[warp - BN] = s;
    }
}

// ---------------------------------------------------------------------------
// K0b: duplicate W_conv scalars into packed (w,w) pairs. 32768 threads.
// ---------------------------------------------------------------------------
__global__ __launch_bounds__(256) void k_wdup(const float* __restrict__ W_conv)
{
    int i = blockIdx.x * 256 + threadIdx.x;   // 0 .. 32767
    float w = W_conv[i];
    g_Wdup[i] = pack2(w, w);
}

// ---------------------------------------------------------------------------
// K1: one warp per (bn, k-quad): 4 neighbor rows in flight,
// 4 interleaved butterflies; lanes 0-3 each finish one k (exp + atomic den).
// ---------------------------------------------------------------------------
__global__ __launch_bounds__(256) void k_logits(
    const int* __restrict__ entity_ids,
    const int* __restrict__ adj_entity,
    const int* __restrict__ adj_relation,
    const float* __restrict__ ent_emb,
    const float* __restrict__ W_att,
    const float* __restrict__ b_att)
{
    int warp = (blockIdx.x * blockDim.x + threadIdx.x) >> 5;  // 0..TOT/4-1
    int lane = threadIdx.x & 31;

    int bn = warp / 5;
    int k0 = (warp - bn * 5) * 4;     // 0,4,8,12,16
    int b  = bn / NN;
    int n  = bn - b * NN;

    int eid = entity_ids[bn];
    int4 nid = *(const int4*)(adj_entity   + eid * KK + k0);  // 16B-aligned
    int4 rid = *(const int4*)(adj_relation + eid * KK + k0);

    float4 wv = ((const float4*)(W_att + DD))[lane];

    float4 v0 = ((const float4*)(ent_emb + (size_t)nid.x * DD))[lane];
    float4 v1 = ((const float4*)(ent_emb + (size_t)nid.y * DD))[lane];
    float4 v2 = ((const float4*)(ent_emb + (size_t)nid.z * DD))[lane];
    float4 v3 = ((const float4*)(ent_emb + (size_t)nid.w * DD))[lane];

    float s0 = v0.x*wv.x + v0.y*wv.y + v0.z*wv.z + v0.w*wv.w;
    float s1 = v1.x*wv.x + v1.y*wv.y + v1.z*wv.z + v1.w*wv.w;
    float s2 = v2.x*wv.x + v2.y*wv.y + v2.z*wv.z + v2.w*wv.w;
    float s3 = v3.x*wv.x + v3.y*wv.y + v3.z*wv.z + v3.w*wv.w;

    #pragma unroll
    for (int off = 16; off > 0; off >>= 1) {
        s0 += __shfl_xor_sync(0xffffffffu, s0, off);
        s1 += __shfl_xor_sync(0xffffffffu, s1, off);
        s2 += __shfl_xor_sync(0xffffffffu, s2, off);
        s3 += __shfl_xor_sync(0xffffffffu, s3, off);
    }

    if (lane < 4) {
        float s  = (lane == 0) ? s0 : (lane == 1) ? s1 : (lane == 2) ? s2 : s3;
        int   rv = (lane == 0) ? rid.x : (lane == 1) ? rid.y
                 : (lane == 2) ? rid.z : rid.w;
        float base = g_ee_dot[bn] + b_att[0];
        float e = __expf(fmaxf(s + base + g_rel_dot[rv], 0.0f));
        int nk = n * KK + k0 + lane;
        g_exp[nk * BB + b] = e;
        atomicAdd(&g_den[nk], e);
    }
}

// ---------------------------------------------------------------------------
// K2: gather. 64-thread block per (b,n); thread = dim pair (2d, 2d+1).
// 20 independent LDG.64 in flight; packed fma.rn.f32x2.
// ---------------------------------------------------------------------------
__global__ __launch_bounds__(64) void k_gather(
    const int* __restrict__ entity_ids,
    const int* __restrict__ adj_entity,
    const float* __restrict__ ent_emb)
{
    __shared__ int s_nid[KK];
    __shared__ ull s_att2[KK];

    int bn = blockIdx.x;
    int b  = bn / NN;
    int n  = bn - b * NN;
    int t  = threadIdx.x;

    int eid = entity_ids[bn];
    if (t < KK) {
        s_nid[t] = adj_entity[eid * KK + t];
        int nk = n * KK + t;
        float a = __fdividef(g_exp[nk * BB + b], g_den[nk]);
        s_att2[t] = pack2(a, a);
    }
    __syncthreads();

    int d0 = 2 * t;
    ull ee2 = *(const ull*)(ent_emb + (size_t)eid * DD + d0);

    ull v[KK];
    #pragma unroll
    for (int k = 0; k < KK; k++)
        v[k] = *(const ull*)(ent_emb + (size_t)s_nid[k] * DD + d0);

    ull acc = 0ull;
    #pragma unroll
    for (int k = 0; k < KK; k++)
        acc = fma2(s_att2[k], v[k], acc);

    *(ull*)(g_agg + (size_t)bn * 2 * DD + d0)      = ee2;
    *(ull*)(g_agg + (size_t)bn * 2 * DD + DD + d0) = acc;
}

// ---------------------------------------------------------------------------
// K3: K-split GEMM partials. blockIdx = tile*2 + ks; tile = 16 rows,
// ks selects j half [ks*128, ks*128+128). 256 threads:
//   p = t&63 -> output pair d0 = 2p; rg = t>>6 -> rows rg*4..rg*4+3.
// Per j: 1 LDS.128 (4 rows packed) + 1 prefetched LDG.128 (dup'd W pair)
//        + 4 FFMA2, zero MOVs.
// ---------------------------------------------------------------------------
#define GROWS  16
#define GPITCH 20     // floats per j-row: 80B (16B-aligned)
#define JH     128    // j per block (K half)

__global__ __launch_bounds__(256) void k_gemm(void)
{
    __shared__ float sT[JH * GPITCH];   // [128][20] = 10 KB

    int t    = threadIdx.x;
    int tile = blockIdx.x >> 1;
    int ks   = blockIdx.x & 1;
    int bn0  = tile * GROWS;

    // stage 16 rows x 128 j (transposed): sT[j][row]
    {
        int row = t & 15;
        int jc  = t >> 4;          // 0..15 -> chunk of 8 j
        const float4* src = (const float4*)(g_agg + (size_t)(bn0 + row) * 2 * DD
                                            + ks * JH + jc * 8);
        #pragma unroll
        for (int c = 0; c < 2; c++) {
            float4 v = src[c];
            int j = jc * 8 + c * 4;
            sT[(j + 0) * GPITCH + row] = v.x;
            sT[(j + 1) * GPITCH + row] = v.y;
            sT[(j + 2) * GPITCH + row] = v.z;
            sT[(j + 3) * GPITCH + row] = v.w;
        }
    }
    __syncthreads();

    int p  = t & 63;          // output pair -> d0 = 2p
    int d0 = 2 * p;
    int rg = t >> 6;          // 0..3 -> rows rg*4 .. rg*4+3

    ull acc[2][2] = {{0ull, 0ull}, {0ull, 0ull}};

    // dup'd W: entry (j*DD + d); ulonglong2 load = (dup w_d0, dup w_d0+1)
    const ulonglong2* Wt = (const ulonglong2*)(g_Wdup + (size_t)ks * JH * DD + d0);
    const float* sb = sT + rg * 4;

    // prologue: prefetch j = 0..3 (4 LDG.128 in flight)
    ulonglong2 wb[4];
    #pragma unroll
    for (int i = 0; i < 4; i++)
        wb[i] = Wt[i * (DD / 2)];

    #pragma unroll 1
    for (int jt = 0; jt < JH; jt += 4) {
        ulonglong2 wc[4];
        #pragma unroll
        for (int i = 0; i < 4; i++) wc[i] = wb[i];

        int jn = (jt + 4) & (JH - 1);   // wrap-around prefetch
        #pragma unroll
        for (int i = 0; i < 4; i++)
            wb[i] = Wt[(jn + i) * (DD / 2)];

        #pragma unroll
        for (int i = 0; i < 4; i++) {
            int j = jt + i;
            ulonglong2 pa = *(const ulonglong2*)(sb + j * GPITCH);  // 4 rows
            acc[0][0] = fma2(pa.x, wc[i].x, acc[0][0]);
            acc[1][0] = fma2(pa.x, wc[i].y, acc[1][0]);
            acc[0][1] = fma2(pa.y, wc[i].x, acc[0][1]);
            acc[1][1] = fma2(pa.y, wc[i].y, acc[1][1]);
        }
    }

    float* dst = g_part[ks];
    #pragma unroll
    for (int rp = 0; rp < 2; rp++) {
        float lo0, hi0, lo1, hi1;
        unpack2(acc[0][rp], lo0, hi0);   // rows r0, r0+1 @ d0
        unpack2(acc[1][rp], lo1, hi1);   // rows r0, r0+1 @ d0+1
        int r0 = bn0 + rg * 4 + rp * 2;
        *(float2*)(dst + (size_t)r0 * DD + d0)       = make_float2(lo0, lo1);
        *(float2*)(dst + (size_t)(r0 + 1) * DD + d0) = make_float2(hi0, hi1);
    }
}

// ---------------------------------------------------------------------------
// K4: fixup. out = relu(p0 + p1 + bias). float4 per thread.
// ---------------------------------------------------------------------------
__global__ __launch_bounds__(256) void k_fix(
    const float* __restrict__ b_conv,
    float* __restrict__ out)
{
    int i  = blockIdx.x * 256 + threadIdx.x;     // 0 .. BN*DD/4-1
    int d4 = (i & 31) * 4;                       // dim of first component

    float4 a = *(const float4*)(g_part[0] + (size_t)i * 4);
    float4 b = *(const float4*)(g_part[1] + (size_t)i * 4);
    float4 c = *(const float4*)(b_conv + d4);

    float4 o;
    o.x = fmaxf(a.x + b.x + c.x, 0.0f);
    o.y = fmaxf(a.y + b.y + c.y, 0.0f);
    o.z = fmaxf(a.z + b.z + c.z, 0.0f);
    o.w = fmaxf(a.w + b.w + c.w, 0.0f);
    *(float4*)(out + (size_t)i * 4) = o;
}

// ---------------------------------------------------------------------------
extern "C" void kernel_launch(void* const* d_in, const int* in_sizes, int n_in,
                              void* d_out, int out_size)
{
    const int*   entity_ids = (const int*)  d_in[0];
    const int*   adj_entity = (const int*)  d_in[1];
    const int*   adj_rel    = (const int*)  d_in[2];
    const float* ent_emb    = (const float*)d_in[3];
    const float* rel_emb    = (const float*)d_in[4];
    const float* W_att      = (const float*)d_in[5];
    const float* b_att      = (const float*)d_in[6];
    const float* W_conv     = (const float*)d_in[7];
    const float* b_conv     = (const float*)d_in[8];
    float* out = (float*)d_out;

    k_pre<<<(BN + 100 + 7) / 8, 256>>>(entity_ids, ent_emb, rel_emb, W_att);

    k_wdup<<<2 * DD * DD / 256, 256>>>(W_conv);

    k_logits<<<TOT / 4 / 8, 256>>>(entity_ids, adj_entity, adj_rel,
                                   ent_emb, W_att, b_att);

    k_gather<<<BN, 64>>>(entity_ids, adj_entity, ent_emb);

    k_gemm<<<(BN / GROWS) * 2, 256>>>();

    k_fix<<<BN * DD / 4 / 256, 256>>>(b_conv, out);
}

// round 11
// speedup vs baseline: 1.6642x; 1.6642x over previous
#include <cuda_runtime.h>
#include <cuda_bf16.h>

#define BB 128   // batch
#define NN 50    // entities per doc
#define KK 20    // neighbors
#define DD 128   // embedding dim
#define NK (NN*KK)          // 1000
#define BN (BB*NN)          // 6400
#define TOT (BB*NN*KK)      // 128000

typedef unsigned long long ull;

// scratch
__device__ float g_exp[TOT];          // transposed: exp(logit)[nk][b]
__device__ float g_den[1024];         // softmax denominators per (n,k)
__device__ float g_ee_dot[BN];
__device__ float g_rel_dot[128];      // R=100, padded

// ---- packed f32x2 helpers (sm_103a) --------------------------------------
__device__ __forceinline__ ull pack2(float lo, float hi) {
    ull r;
    asm("mov.b64 %0, {%1, %2};" : "=l"(r) : "f"(lo), "f"(hi));
    return r;
}
__device__ __forceinline__ void unpack2(ull v, float& lo, float& hi) {
    asm("mov.b64 {%0, %1}, %2;" : "=f"(lo), "=f"(hi) : "l"(v));
}
__device__ __forceinline__ ull fma2(ull a, ull b, ull c) {
    ull d;
    asm("fma.rn.f32x2 %0, %1, %2, %3;" : "=l"(d) : "l"(a), "l"(b), "l"(c));
    return d;
}

// ---------------------------------------------------------------------------
// K0: zero g_den; ee_dot[bn] = dot(ee, w0); rel_dot[r] = dot(rel_emb[r], w2)
// ---------------------------------------------------------------------------
__global__ __launch_bounds__(256) void k_pre(
    const int* __restrict__ entity_ids,
    const float* __restrict__ ent_emb,
    const float* __restrict__ rel_emb,
    const float* __restrict__ W_att)
{
    int gtid = blockIdx.x * 256 + threadIdx.x;
    if (gtid < 1024) g_den[gtid] = 0.0f;

    int warp = gtid >> 5;
    int lane = threadIdx.x & 31;
    if (warp >= BN + 100) return;

    const float4* row;
    const float4* w;
    if (warp < BN) {
        int eid = entity_ids[warp];
        row = (const float4*)(ent_emb + (size_t)eid * DD);
        w   = (const float4*)(W_att);            // w0
    } else {
        row = (const float4*)(rel_emb + (size_t)(warp - BN) * DD);
        w   = (const float4*)(W_att + 2 * DD);   // w2
    }
    float4 a = row[lane], wv = w[lane];
    float s = a.x*wv.x + a.y*wv.y + a.z*wv.z + a.w*wv.w;
    #pragma unroll
    for (int off = 16; off > 0; off >>= 1)
        s += __shfl_xor_sync(0xffffffffu, s, off);
    if (lane == 0) {
        if (warp < BN) g_ee_dot[warp] = s;
        else           g_rel_dot[warp - BN] = s;
    }
}

// ---------------------------------------------------------------------------
// K1: one warp per (bn, k-quad): 4 neighbor rows in flight,
// 4 interleaved butterflies; lanes 0-3 each finish one k (exp + atomic den).
// ---------------------------------------------------------------------------
__global__ __launch_bounds__(256) void k_logits(
    const int* __restrict__ entity_ids,
    const int* __restrict__ adj_entity,
    const int* __restrict__ adj_relation,
    const float* __restrict__ ent_emb,
    const float* __restrict__ W_att,
    const float* __restrict__ b_att)
{
    int warp = (blockIdx.x * blockDim.x + threadIdx.x) >> 5;  // 0..TOT/4-1
    int lane = threadIdx.x & 31;

    int bn = warp / 5;
    int k0 = (warp - bn * 5) * 4;     // 0,4,8,12,16
    int b  = bn / NN;
    int n  = bn - b * NN;

    int eid = entity_ids[bn];
    int4 nid = *(const int4*)(adj_entity   + eid * KK + k0);  // 16B-aligned
    int4 rid = *(const int4*)(adj_relation + eid * KK + k0);

    float4 wv = ((const float4*)(W_att + DD))[lane];

    float4 v0 = ((const float4*)(ent_emb + (size_t)nid.x * DD))[lane];
    float4 v1 = ((const float4*)(ent_emb + (size_t)nid.y * DD))[lane];
    float4 v2 = ((const float4*)(ent_emb + (size_t)nid.z * DD))[lane];
    float4 v3 = ((const float4*)(ent_emb + (size_t)nid.w * DD))[lane];

    float s0 = v0.x*wv.x + v0.y*wv.y + v0.z*wv.z + v0.w*wv.w;
    float s1 = v1.x*wv.x + v1.y*wv.y + v1.z*wv.z + v1.w*wv.w;
    float s2 = v2.x*wv.x + v2.y*wv.y + v2.z*wv.z + v2.w*wv.w;
    float s3 = v3.x*wv.x + v3.y*wv.y + v3.z*wv.z + v3.w*wv.w;

    #pragma unroll
    for (int off = 16; off > 0; off >>= 1) {
        s0 += __shfl_xor_sync(0xffffffffu, s0, off);
        s1 += __shfl_xor_sync(0xffffffffu, s1, off);
        s2 += __shfl_xor_sync(0xffffffffu, s2, off);
        s3 += __shfl_xor_sync(0xffffffffu, s3, off);
    }

    if (lane < 4) {
        float s  = (lane == 0) ? s0 : (lane == 1) ? s1 : (lane == 2) ? s2 : s3;
        int   rv = (lane == 0) ? rid.x : (lane == 1) ? rid.y
                 : (lane == 2) ? rid.z : rid.w;
        float base = g_ee_dot[bn] + b_att[0];
        float e = __expf(fmaxf(s + base + g_rel_dot[rv], 0.0f));
        int nk = n * KK + k0 + lane;
        g_exp[nk * BB + b] = e;
        atomicAdd(&g_den[nk], e);
    }
}

// ---------------------------------------------------------------------------
// K2: fused gather + gemm. One block per 16 (b,n) rows, 128 threads, grid 400.
//
// Phase A (stage): s_eid[16], s_nid[320], s_att2[320] (dup'd packed att).
// Phase B (gather): thread = (d-pair p = t&63, half = t>>6 -> 8 rows each).
//   Per row: 20 independent LDG.64 + packed FMA; writes ee/nb directly into
//   the transposed gemm tile sT[j][row] (j in [0,256), pitch 20).
// Phase C (gemm): round-7 inner loop:
//   thread = (d0 = 2*(t&63), rg = t>>6 -> rows rg*8..rg*8+7),
//   W register-prefetched 8 deep, 8 FFMA2 per j.
// ---------------------------------------------------------------------------
#define GROWS  16
#define GPITCH 20     // floats per j-row: 80B (16B-aligned)

__global__ __launch_bounds__(128) void k_gg(
    const int* __restrict__ entity_ids,
    const int* __restrict__ adj_entity,
    const float* __restrict__ ent_emb,
    const float* __restrict__ W_conv,
    const float* __restrict__ b_conv,
    float* __restrict__ out)
{
    __shared__ float sT[2 * DD * GPITCH];   // [256][20] = 20 KB
    __shared__ int   s_eid[GROWS];
    __shared__ int   s_nid[GROWS * KK];     // 320
    __shared__ ull   s_att2[GROWS * KK];    // 320 dup'd att pairs

    int t   = threadIdx.x;
    int bn0 = blockIdx.x * GROWS;

    // ---- Phase A: stage ids + normalized attention weights ----
    if (t < GROWS) s_eid[t] = entity_ids[bn0 + t];
    for (int i = t; i < GROWS * KK; i += 128) {
        int rl = i / KK;            // row in tile
        int k  = i - rl * KK;
        int bn = bn0 + rl;
        int b  = bn / NN;
        int n  = bn - b * NN;
        int eid = entity_ids[bn];
        s_nid[i] = adj_entity[eid * KK + k];
        int nk = n * KK + k;
        float a = __fdividef(g_exp[nk * BB + b], g_den[nk]);
        s_att2[i] = pack2(a, a);
    }
    __syncthreads();

    int p    = t & 63;      // d-pair index: d0 = 2p
    int half = t >> 6;      // 0/1 -> rows half*8 .. half*8+7
    int d0   = 2 * p;

    // ---- Phase B: gather 8 rows, write transposed tile ----
    #pragma unroll 1
    for (int m = 0; m < 8; m++) {
        int r  = half * 8 + m;
        int eid = s_eid[r];

        ull ee2 = *(const ull*)(ent_emb + (size_t)eid * DD + d0);

        ull v[KK];
        #pragma unroll
        for (int k = 0; k < KK; k++)
            v[k] = *(const ull*)(ent_emb + (size_t)s_nid[r * KK + k] * DD + d0);

        ull acc = 0ull;
        #pragma unroll
        for (int k = 0; k < KK; k++)
            acc = fma2(s_att2[r * KK + k], v[k], acc);

        float elo, ehi, nlo, nhi;
        unpack2(ee2, elo, ehi);
        unpack2(acc, nlo, nhi);
        sT[(d0 + 0) * GPITCH + r]      = elo;
        sT[(d0 + 1) * GPITCH + r]      = ehi;
        sT[(DD + d0 + 0) * GPITCH + r] = nlo;
        sT[(DD + d0 + 1) * GPITCH + r] = nhi;
    }
    __syncthreads();

    // ---- Phase C: gemm (round-7 inner loop) ----
    int rg = half;            // rows rg*8 .. rg*8+7

    ull acc[2][4];
    {
        ull i0 = pack2(b_conv[d0],     b_conv[d0]);
        ull i1 = pack2(b_conv[d0 + 1], b_conv[d0 + 1]);
        #pragma unroll
        for (int rp = 0; rp < 4; rp++) { acc[0][rp] = i0; acc[1][rp] = i1; }
    }

    const float* Wp = W_conv + d0;
    const float* sb = sT + rg * 8;

    // prologue: fill prefetch buffer with j = 0..7
    float2 wb[8];
    #pragma unroll
    for (int i = 0; i < 8; i++)
        wb[i] = *(const float2*)(Wp + i * DD);

    #pragma unroll 1
    for (int jt = 0; jt < 2 * DD; jt += 8) {
        float2 wc[8];
        #pragma unroll
        for (int i = 0; i < 8; i++) wc[i] = wb[i];

        // branchless wrap-around prefetch of next chunk (8 LDG.64 in flight)
        int jn = (jt + 8) & (2 * DD - 1);
        #pragma unroll
        for (int i = 0; i < 8; i++)
            wb[i] = *(const float2*)(Wp + (jn + i) * DD);

        #pragma unroll
        for (int i = 0; i < 8; i++) {
            int j = jt + i;
            ull w0 = pack2(wc[i].x, wc[i].x);
            ull w1 = pack2(wc[i].y, wc[i].y);
            ulonglong2 pa = *(const ulonglong2*)(sb + j * GPITCH);       // rows 0-3
            ulonglong2 pb = *(const ulonglong2*)(sb + j * GPITCH + 4);   // rows 4-7
            acc[0][0] = fma2(pa.x, w0, acc[0][0]);
            acc[1][0] = fma2(pa.x, w1, acc[1][0]);
            acc[0][1] = fma2(pa.y, w0, acc[0][1]);
            acc[1][1] = fma2(pa.y, w1, acc[1][1]);
            acc[0][2] = fma2(pb.x, w0, acc[0][2]);
            acc[1][2] = fma2(pb.x, w1, acc[1][2]);
            acc[0][3] = fma2(pb.y, w0, acc[0][3]);
            acc[1][3] = fma2(pb.y, w1, acc[1][3]);
        }
    }

    #pragma unroll
    for (int rp = 0; rp < 4; rp++) {
        float lo0, hi0, lo1, hi1;
        unpack2(acc[0][rp], lo0, hi0);   // rows r0, r0+1 @ d0
        unpack2(acc[1][rp], lo1, hi1);   // rows r0, r0+1 @ d0+1
        int r0 = bn0 + rg * 8 + rp * 2;
        float2 o0 = make_float2(fmaxf(lo0, 0.0f), fmaxf(lo1, 0.0f));
        float2 o1 = make_float2(fmaxf(hi0, 0.0f), fmaxf(hi1, 0.0f));
        *(float2*)(out + (size_t)r0 * DD + d0)       = o0;
        *(float2*)(out + (size_t)(r0 + 1) * DD + d0) = o1;
    }
}

// ---------------------------------------------------------------------------
extern "C" void kernel_launch(void* const* d_in, const int* in_sizes, int n_in,
                              void* d_out, int out_size)
{
    const int*   entity_ids = (const int*)  d_in[0];
    const int*   adj_entity = (const int*)  d_in[1];
    const int*   adj_rel    = (const int*)  d_in[2];
    const float* ent_emb    = (const float*)d_in[3];
    const float* rel_emb    = (const float*)d_in[4];
    const float* W_att      = (const float*)d_in[5];
    const float* b_att      = (const float*)d_in[6];
    const float* W_conv     = (const float*)d_in[7];
    const float* b_conv     = (const float*)d_in[8];
    float* out = (float*)d_out;

    k_pre<<<(BN + 100 + 7) / 8, 256>>>(entity_ids, ent_emb, rel_emb, W_att);

    k_logits<<<TOT / 4 / 8, 256>>>(entity_ids, adj_entity, adj_rel,
                                   ent_emb, W_att, b_att);

    k_gg<<<BN / GROWS, 128>>>(entity_ids, adj_entity, ent_emb,
                              W_conv, b_conv, out);
}